// round 6
// baseline (speedup 1.0000x reference)
#include <cuda_runtime.h>
#include <math.h>

// ---------------------------------------------------------------------------
// FraudNATHybridModel — R6: R5 packed-f32x2 convs with the float4-zero-fill
// alignment bug fixed (sh1p was float2/8B-aligned, cast to float4 -> ST.128
// misaligned trap). All packed operands still come directly from LDS.64.
// ---------------------------------------------------------------------------

#define BMAX 8192

__device__ float2 g_U[256];
__device__ float  g_z[BMAX * 4];
__device__ float  g_coef[8];

#define UNPACK2(lo, hi, in) \
    do { unsigned _ulo, _uhi; \
         asm("mov.b64 {%0, %1}, %2;" : "=r"(_ulo), "=r"(_uhi) : "l"(in)); \
         lo = __uint_as_float(_ulo); hi = __uint_as_float(_uhi); } while (0)
#define FMA2(acc, a, b) \
    asm("fma.rn.f32x2 %0, %1, %2, %0;" : "+l"(acc) : "l"(a), "l"(b))

__device__ __forceinline__ unsigned long long lds64(const void* p) {
    unsigned long long v;
    unsigned a = (unsigned)__cvta_generic_to_shared(p);
    asm volatile("ld.shared.b64 %0, [%1];" : "=l"(v) : "r"(a));
    return v;
}

__device__ __forceinline__ float2 cmul(float2 a, float2 b) {
    return make_float2(a.x * b.x - a.y * b.y, a.x * b.y + a.y * b.x);
}
__device__ __forceinline__ float2 cadd(float2 a, float2 b) {
    return make_float2(a.x + b.x, a.y + b.y);
}
__device__ __forceinline__ float2 cfma_(float2 a, float2 b, float2 c) {
    c.x += a.x * b.x - a.y * b.y;
    c.y += a.x * b.y + a.y * b.x;
    return c;
}

// ------------------------- MT19937 (numpy legacy) --------------------------
__device__ unsigned mt_next(unsigned* mt, int* mti) {
    if (*mti >= 624) {
        for (int i = 0; i < 624; i++) {
            unsigned y = (mt[i] & 0x80000000u) | (mt[(i + 1) % 624] & 0x7fffffffu);
            unsigned v = mt[(i + 397) % 624] ^ (y >> 1);
            if (y & 1u) v ^= 0x9908b0dfu;
            mt[i] = v;
        }
        *mti = 0;
    }
    unsigned y = mt[(*mti)++];
    y ^= y >> 11;
    y ^= (y << 7) & 0x9d2c5680u;
    y ^= (y << 15) & 0xefc60000u;
    y ^= y >> 18;
    return y;
}

__device__ void ap1(float2* s, int w, float2 u00, float2 u01, float2 u10, float2 u11) {
    int m = 8 >> w;
    for (int i = 0; i < 16; i++) {
        if (!(i & m)) {
            float2 a = s[i], b = s[i | m];
            s[i]     = cadd(cmul(u00, a), cmul(u01, b));
            s[i | m] = cadd(cmul(u10, a), cmul(u11, b));
        }
    }
}
__device__ void ap2(float2* s, int wc, int wt, float2 u00, float2 u01, float2 u10, float2 u11) {
    int mc = 8 >> wc, mt2 = 8 >> wt;
    for (int i = 0; i < 16; i++) {
        if ((i & mc) && !(i & mt2)) {
            float2 a = s[i], b = s[i | mt2];
            s[i]       = cadd(cmul(u00, a), cmul(u01, b));
            s[i | mt2] = cadd(cmul(u10, a), cmul(u11, b));
        }
    }
}

// ------------------------- K0: build U_post --------------------------------
__global__ void k_setup(const float* __restrict__ gate_params,
                        const float* __restrict__ rand_params) {
    __shared__ unsigned smt[624];
    __shared__ int sg[50], sw0[50], sw1[50], sp[50];
    int tid = threadIdx.x;

    if (tid == 0) {
        smt[0] = 12345u;
        for (int i = 1; i < 624; i++)
            smt[i] = 1812433253u * (smt[i - 1] ^ (smt[i - 1] >> 30)) + (unsigned)i;
        int mti = 624;
        int p = 0;
        for (int k = 0; k < 50; k++) {
            unsigned g;
            do { g = mt_next(smt, &mti) & 7u; } while (g > 4u);
            int w0, w1 = -1;
            if (g >= 3u) {
                int arr[4] = {0, 1, 2, 3};
                for (int i = 3; i >= 1; --i) {
                    unsigned mask = (unsigned)i;
                    mask |= mask >> 1; mask |= mask >> 2; mask |= mask >> 4;
                    unsigned j;
                    do { j = mt_next(smt, &mti) & mask; } while (j > (unsigned)i);
                    int t = arr[i]; arr[i] = arr[j]; arr[j] = t;
                }
                w0 = arr[0]; w1 = arr[1];
            } else {
                w0 = (int)(mt_next(smt, &mti) & 3u);
            }
            sg[k] = (int)g; sw0[k] = w0; sw1[k] = w1;
            sp[k] = (g == 4u) ? -1 : p++;
        }
    }
    __syncthreads();

    if (tid < 16) {
        float2 st[16];
        for (int i = 0; i < 16; i++) st[i] = make_float2(i == tid ? 1.f : 0.f, 0.f);

        for (int k = 0; k < 50; k++) {
            int g = sg[k], w0 = sw0[k], w1 = sw1[k];
            float t = (sp[k] >= 0) ? rand_params[sp[k]] : 0.f;
            float sn, cs;
            sincosf(0.5f * t, &sn, &cs);
            if (g == 0) {
                ap1(st, w0, make_float2(cs, 0), make_float2(0, -sn),
                            make_float2(0, -sn), make_float2(cs, 0));
            } else if (g == 1) {
                ap1(st, w0, make_float2(cs, 0), make_float2(-sn, 0),
                            make_float2(sn, 0), make_float2(cs, 0));
            } else if (g == 2) {
                ap1(st, w0, make_float2(cs, -sn), make_float2(0, 0),
                            make_float2(0, 0), make_float2(cs, sn));
            } else if (g == 3) {
                ap2(st, w0, w1, make_float2(cs, 0), make_float2(0, -sn),
                                make_float2(0, -sn), make_float2(cs, 0));
            } else {
                ap2(st, w0, w1, make_float2(0, 0), make_float2(1, 0),
                                make_float2(1, 0), make_float2(0, 0));
            }
        }
        float sn, cs;
        sincosf(0.5f * gate_params[0], &sn, &cs);
        ap1(st, 0, make_float2(cs, 0), make_float2(0, -sn), make_float2(0, -sn), make_float2(cs, 0));
        sincosf(0.5f * gate_params[1], &sn, &cs);
        ap1(st, 1, make_float2(cs, 0), make_float2(-sn, 0), make_float2(sn, 0), make_float2(cs, 0));
        sincosf(0.5f * gate_params[2], &sn, &cs);
        ap1(st, 3, make_float2(cs, -sn), make_float2(0, 0), make_float2(0, 0), make_float2(cs, sn));
        sincosf(0.5f * gate_params[3], &sn, &cs);
        ap2(st, 0, 2, make_float2(cs, 0), make_float2(0, -sn), make_float2(0, -sn), make_float2(cs, 0));
        const float r = 0.70710678118654752f;
        ap1(st, 3, make_float2(r, 0), make_float2(r, 0), make_float2(r, 0), make_float2(-r, 0));
        ap1(st, 2, make_float2(0.5f, 0.5f), make_float2(0.5f, -0.5f),
                   make_float2(0.5f, -0.5f), make_float2(0.5f, 0.5f));
        ap2(st, 3, 0, make_float2(0, 0), make_float2(1, 0), make_float2(1, 0), make_float2(0, 0));

        for (int i = 0; i < 16; i++) g_U[i * 16 + tid] = st[i];
    }
}

// ------------------------- K1: fused per-image pipeline --------------------
// sxp[j][c]: (x[j-1][c-1], x[j][c-1]) vertical input pairs, zero-padded.
// sh1p[ic*16 + y+1][c]: (m,m) duplicated conv1 pooled values, zero-padded.
// sw2p[k][cp]: (w2[2cp][k], w2[2cp+1][k]) channel-pair weights.
__global__ __launch_bounds__(128) void k_main(const float* __restrict__ x,
                                              const float* __restrict__ w1,
                                              const float* __restrict__ b1,
                                              const float* __restrict__ w2,
                                              const float* __restrict__ b2) {
    __shared__ __align__(16) float2 sxp[29][31];
    __shared__ __align__(16) float2 sh1p[128][17];
    __shared__ float2 sw1p[72];          // (w,w)
    __shared__ float2 sb1p[8];           // (b,b)
    __shared__ float2 sw2p[72][8];
    __shared__ float2 sb2p[8];           // (b_c0, b_c1)
    __shared__ float shm[16 * 14 * 7];
    __shared__ float spart[112];
    __shared__ float spool[16];
    __shared__ float2 sv[8];
    __shared__ float2 sphi[16];

    int tid = threadIdx.x;
    int b = blockIdx.x;
    const float* xb = x + (size_t)b * 784;

    // ---- zero padded arrays (float2 stores only: 8B-safe) ----
    {
        float2 z2 = make_float2(0.f, 0.f);
        float2* p1 = &sxp[0][0];
        for (int i = tid; i < 29 * 31; i += 128) p1[i] = z2;
        float2* p2 = &sh1p[0][0];
        for (int i = tid; i < 128 * 17; i += 128) p2[i] = z2;
    }
    // ---- stage weights ----
    for (int i = tid; i < 72; i += 128) { float w = w1[i]; sw1p[i] = make_float2(w, w); }
    if (tid < 8)  { float v = b1[tid]; sb1p[tid] = make_float2(v, v); }
    for (int i = tid; i < 576; i += 128) {
        int k = i >> 3, cp = i & 7;
        sw2p[k][cp] = make_float2(w2[(2 * cp) * 72 + k], w2[(2 * cp + 1) * 72 + k]);
    }
    if (tid < 8)  sb2p[tid] = make_float2(b2[2 * tid], b2[2 * tid + 1]);
    __syncthreads();

    // ---- scatter input into vertical pairs ----
    for (int i = tid; i < 784; i += 128) {
        int r = i / 28, c = i % 28;
        float v = xb[i];
        sxp[r + 1][c + 1].x = v;
        sxp[r][c + 1].y = v;
    }
    __syncthreads();

    // ---- conv1 (packed vertical row pairs) + relu + maxpool -> sh1p ----
    if (tid < 112) {
        int c = tid / 14, y = tid % 14;
        unsigned long long wp[9];
#pragma unroll
        for (int k = 0; k < 9; k++) wp[k] = lds64(&sw1p[c * 9 + k]);
        unsigned long long bias2 = lds64(&sb1p[c]);
        float pooled[14];
#pragma unroll
        for (int h = 0; h < 2; h++) {
            unsigned long long cr[14];
#pragma unroll
            for (int i = 0; i < 14; i++) cr[i] = bias2;
#pragma unroll
            for (int ky = 0; ky < 3; ky++) {
                int j = 2 * y + ky;
                unsigned long long rp[16];
#pragma unroll
                for (int i = 0; i < 16; i++) rp[i] = lds64(&sxp[j][14 * h + i]);
#pragma unroll
                for (int kx = 0; kx < 3; kx++) {
                    unsigned long long w = wp[ky * 3 + kx];
#pragma unroll
                    for (int i = 0; i < 14; i++) FMA2(cr[i], w, rp[i + kx]);
                }
            }
#pragma unroll
            for (int o = 0; o < 7; o++) {
                float l0, h0, l1, h1;
                UNPACK2(l0, h0, cr[2 * o]);
                UNPACK2(l1, h1, cr[2 * o + 1]);
                pooled[h * 7 + o] = fmaxf(fmaxf(fmaxf(l0, h0), fmaxf(l1, h1)), 0.f);
            }
        }
        float2* row = sh1p[c * 16 + y + 1];
#pragma unroll
        for (int i = 0; i < 14; i++) row[i + 1] = make_float2(pooled[i], pooled[i]);
    }
    __syncthreads();

    // ---- conv2 (packed channel pairs) + horizontal pair-max -> shm ----
    if (tid < 112) {
        int cp = tid / 14, y = tid % 14;
        unsigned long long acc[14];
        {
            unsigned long long bias2 = lds64(&sb2p[cp]);
#pragma unroll
            for (int i = 0; i < 14; i++) acc[i] = bias2;
        }
#pragma unroll
        for (int ic = 0; ic < 8; ic++) {
#pragma unroll
            for (int ky = 0; ky < 3; ky++) {
                const float2* rowp = sh1p[ic * 16 + y + ky];
                unsigned long long rp[16];
#pragma unroll
                for (int i = 0; i < 16; i++) rp[i] = lds64(&rowp[i]);
#pragma unroll
                for (int kx = 0; kx < 3; kx++) {
                    unsigned long long w = lds64(&sw2p[ic * 9 + ky * 3 + kx][cp]);
#pragma unroll
                    for (int i = 0; i < 14; i++) FMA2(acc[i], w, rp[i + kx]);
                }
            }
        }
#pragma unroll
        for (int o = 0; o < 7; o++) {
            float a0l, a1l, a0h, a1h;
            UNPACK2(a0l, a1l, acc[2 * o]);
            UNPACK2(a0h, a1h, acc[2 * o + 1]);
            shm[((2 * cp) * 14 + y) * 7 + o]     = fmaxf(a0l, a0h);
            shm[((2 * cp + 1) * 14 + y) * 7 + o] = fmaxf(a1l, a1h);
        }
    }
    __syncthreads();

    // ---- vertical max of row pairs + relu + row sum -> spart ----
    if (tid < 112) {
        int c = tid / 7, y2 = tid % 7;
        const float* r0 = &shm[(c * 14 + 2 * y2) * 7];
        const float* r1 = r0 + 7;
        float psum = 0.f;
#pragma unroll
        for (int i = 0; i < 7; i++)
            psum += fmaxf(fmaxf(r0[i], r1[i]), 0.f);
        spart[c * 7 + y2] = psum;
    }
    __syncthreads();

    if (tid < 16) {
        float s = 0.f;
#pragma unroll
        for (int j = 0; j < 7; j++) s += spart[tid * 7 + j];
        spool[tid] = s * (1.f / 49.f);
    }
    __syncthreads();

    // ---- quantum: product-state encoder, psi = U_post * phi, Z expectations
    if (tid < 32) {
        int lane = tid;
        if (lane < 4) {
            float aa = spool[lane], bb = spool[4 + lane],
                  cc = spool[8 + lane], dd = spool[12 + lane];
            float sa, ca, sb, cb, sc, ccs, sd, cd;
            sincosf(0.5f * aa, &sa, &ca);
            sincosf(0.5f * bb, &sb, &cb);
            sincosf(0.5f * cc, &sc, &ccs);
            sincosf(0.5f * dd, &sd, &cd);
            float2 v0 = make_float2(ca * cb, -ca * sb);
            float2 v1 = make_float2(sa * cb, sa * sb);
            float2 t0 = make_float2(ccs * v0.x + sc * v1.y, ccs * v0.y - sc * v1.x);
            float2 t1 = make_float2(sc * v0.y + ccs * v1.x, -sc * v0.x + ccs * v1.y);
            float2 u0 = make_float2(cd * t0.x - sd * t1.x, cd * t0.y - sd * t1.y);
            float2 u1 = make_float2(sd * t0.x + cd * t1.x, sd * t0.y + cd * t1.y);
            sv[2 * lane] = u0;
            sv[2 * lane + 1] = u1;
        }
        __syncwarp();
        if (lane < 16) {
            float2 f0 = sv[0 + ((lane >> 3) & 1)];
            float2 f1 = sv[2 + ((lane >> 2) & 1)];
            float2 f2 = sv[4 + ((lane >> 1) & 1)];
            float2 f3 = sv[6 + (lane & 1)];
            sphi[lane] = cmul(cmul(f0, f1), cmul(f2, f3));
        }
        __syncwarp();
        float p = 0.f;
        if (lane < 16) {
            float2 psi = make_float2(0.f, 0.f);
#pragma unroll
            for (int j = 0; j < 16; j++) psi = cfma_(g_U[lane * 16 + j], sphi[j], psi);
            p = psi.x * psi.x + psi.y * psi.y;
        }
#pragma unroll
        for (int w = 0; w < 4; w++) {
            float sgn = ((lane >> (3 - w)) & 1) ? -p : p;
#pragma unroll
            for (int off = 16; off > 0; off >>= 1)
                sgn += __shfl_xor_sync(0xffffffffu, sgn, off);
            if (lane == 0) g_z[b * 4 + w] = sgn;
        }
    }
}

// ------------------------- K2: BN stats + fold into coefficients -----------
__global__ void k_reduce(const float* __restrict__ gam, const float* __restrict__ bet,
                         const float* __restrict__ fcw, const float* __restrict__ fcb,
                         int B) {
    __shared__ double red[256 * 8];
    int tid = threadIdx.x;
    double sm[4] = {0, 0, 0, 0}, sq[4] = {0, 0, 0, 0};
    for (int r = tid; r < B; r += 256) {
#pragma unroll
        for (int j = 0; j < 4; j++) {
            double v = (double)g_z[r * 4 + j];
            sm[j] += v;
            sq[j] += v * v;
        }
    }
#pragma unroll
    for (int j = 0; j < 4; j++) { red[tid * 8 + j] = sm[j]; red[tid * 8 + 4 + j] = sq[j]; }
    __syncthreads();
    for (int s = 128; s > 0; s >>= 1) {
        if (tid < s) {
#pragma unroll
            for (int j = 0; j < 8; j++) red[tid * 8 + j] += red[(tid + s) * 8 + j];
        }
        __syncthreads();
    }
    if (tid == 0) {
        double invB = 1.0 / (double)B;
        double csum = (double)fcb[0];
        for (int j = 0; j < 4; j++) {
            double mu = red[j] * invB;
            double var = red[4 + j] * invB - mu * mu;
            double sc = (double)gam[j] / sqrt(var + 1e-5);
            g_coef[j] = (float)((double)fcw[j] * sc);
            csum += (double)fcw[j] * ((double)bet[j] - mu * sc);
        }
        g_coef[4] = (float)csum;
    }
}

// ------------------------- K3: final output --------------------------------
__global__ void k_final(float* __restrict__ out, int B) {
    int b = blockIdx.x * blockDim.x + threadIdx.x;
    if (b < B) {
        out[b] = g_coef[4]
               + g_coef[0] * g_z[b * 4 + 0]
               + g_coef[1] * g_z[b * 4 + 1]
               + g_coef[2] * g_z[b * 4 + 2]
               + g_coef[3] * g_z[b * 4 + 3];
    }
}

extern "C" void kernel_launch(void* const* d_in, const int* in_sizes, int n_in,
                              void* d_out, int out_size) {
    const float* x   = (const float*)d_in[0];
    const float* c1w = (const float*)d_in[1];
    const float* c1b = (const float*)d_in[2];
    const float* c2w = (const float*)d_in[3];
    const float* c2b = (const float*)d_in[4];
    const float* gp  = (const float*)d_in[5];
    const float* rp  = (const float*)d_in[6];
    const float* gam = (const float*)d_in[7];
    const float* bet = (const float*)d_in[8];
    const float* fcw = (const float*)d_in[9];
    const float* fcb = (const float*)d_in[10];

    int B = in_sizes[0] / 784;
    if (B > BMAX) B = BMAX;

    k_setup<<<1, 32>>>(gp, rp);
    k_main<<<B, 128>>>(x, c1w, c1b, c2w, c2b);
    k_reduce<<<1, 256>>>(gam, bet, fcw, fcb, B);
    k_final<<<(B + 255) / 256, 256>>>((float*)d_out, B);
}